// round 11
// baseline (speedup 1.0000x reference)
#include <cuda_runtime.h>
#include <cuda_bf16.h>
#include <math.h>

// Problem constants (fixed by the reference setup_inputs)
#define E_  3
#define B_  4096
#define D_  1024
#define M_  5
#define N_  256

#define NB_ALL 608          // every block does dot work; last 96 also do sim
#define NB_A 224            // blocks [0,224):   6 batches (24 pairs/thread)
#define NB_B 288            // blocks [224,512): 5 batches (20 pairs/thread)
#define NB_SIMBASE 512      // blocks [512,608): 3 batches (12 pairs) + sim
#define TPB 256

// exact cover: 224*24 + 288*20 + 96*12 = 12288 pairs per thread-column
//              * 256 threads = 3,145,728 float4 pairs  ✓

// Scratch (allocation-free rule: __device__ globals)
__device__ float g_dot_partial[NB_ALL];
__device__ float g_dotmn[E_][M_][N_];   // raw dot(gt_local[m], feature_local[n])
__device__ float g_fnorm2[E_][N_];      // ||f_n||^2
__device__ float g_ot[E_];

static __device__ __forceinline__ float dot4(float4 a, float4 b) {
    return a.x * b.x + a.y * b.y + a.z * b.z + a.w * b.w;
}

// ---------------------------------------------------------------------------
// Kernel 1: every block streams a contiguous slice of feature*gt with
// 8 front-batched LDG.128 per 4-pair batch (proven optimal). Blocks
// [512,608) carry a reduced dot share and then compute the sim raw dots
// + feature_local row norms (dot FIRST so their loads join the stream early).
// ---------------------------------------------------------------------------
__global__ void __launch_bounds__(TPB, 4) k_main(
    const float* __restrict__ feature,
    const float* __restrict__ gt,
    const float* __restrict__ gt_local,
    const float* __restrict__ feature_local)
{
    const int b = blockIdx.x;
    const int tid = threadIdx.x;
    const int w = tid >> 5;
    const int lane = tid & 31;

    // ---- big streaming reduction: sum(feature * gt), balanced partition ----
    int iters, start4;
    if (b < NB_A) {
        iters = 6;
        start4 = b * (6 * 4 * TPB);                                   // b*6144
    } else if (b < NB_SIMBASE) {
        iters = 5;
        start4 = NB_A * 6144 + (b - NB_A) * (5 * 4 * TPB);            // +*5120
    } else {
        iters = 3;
        start4 = NB_A * 6144 + NB_B * 5120 + (b - NB_SIMBASE) * (3 * 4 * TPB);
    }

    const float4* fa = reinterpret_cast<const float4*>(feature);
    const float4* ga = reinterpret_cast<const float4*>(gt);
    int i = start4 + tid;
    float acc0 = 0.f, acc1 = 0.f, acc2 = 0.f, acc3 = 0.f;
    #pragma unroll 1
    for (int k = 0; k < iters; ++k) {
        // 8 independent 16B loads front-batched (read-once: evict-first)
        float4 x0 = __ldcs(&fa[i]);
        float4 x1 = __ldcs(&fa[i + TPB]);
        float4 x2 = __ldcs(&fa[i + 2 * TPB]);
        float4 x3 = __ldcs(&fa[i + 3 * TPB]);
        float4 y0 = __ldcs(&ga[i]);
        float4 y1 = __ldcs(&ga[i + TPB]);
        float4 y2 = __ldcs(&ga[i + 2 * TPB]);
        float4 y3 = __ldcs(&ga[i + 3 * TPB]);
        acc0 += dot4(x0, y0);
        acc1 += dot4(x1, y1);
        acc2 += dot4(x2, y2);
        acc3 += dot4(x3, y3);
        i += 4 * TPB;
    }
    float acc = (acc0 + acc1) + (acc2 + acc3);

    __shared__ float sh[TPB];
    sh[tid] = acc;
    __syncthreads();
    #pragma unroll
    for (int s = TPB / 2; s > 0; s >>= 1) {
        if (tid < s) sh[tid] += sh[tid + s];
        __syncthreads();
    }
    if (tid == 0) g_dot_partial[b] = sh[0];

    // ---- sim raw dots + feature_local row norms (sim blocks, dot done) ----
    if (b >= NB_SIMBASE) {
        const int sb = b - NB_SIMBASE;      // 0..95
        const int e  = sb / 32;             // 3 extractors
        const int n  = (sb % 32) * 8 + w;   // 0..255

        const float* __restrict__ f = feature_local + ((size_t)e * N_ + n) * D_;
        const float* __restrict__ g = gt_local + (size_t)e * M_ * D_;

        float accm[M_] = {0.f, 0.f, 0.f, 0.f, 0.f};
        float fn = 0.f;
        for (int d = lane; d < D_; d += 32) {
            float fv = f[d];
            fn += fv * fv;
            #pragma unroll
            for (int m = 0; m < M_; m++)
                accm[m] += g[m * D_ + d] * fv;
        }
        #pragma unroll
        for (int off = 16; off > 0; off >>= 1) {
            fn += __shfl_down_sync(0xFFFFFFFFu, fn, off);
            #pragma unroll
            for (int m = 0; m < M_; m++)
                accm[m] += __shfl_down_sync(0xFFFFFFFFu, accm[m], off);
        }
        if (lane == 0) {
            #pragma unroll
            for (int m = 0; m < M_; m++)
                g_dotmn[e][m][n] = accm[m];
            g_fnorm2[e][n] = fn;
        }
    }
}

// ---------------------------------------------------------------------------
// Kernel 2: per-extractor Sinkhorn (one 256-thread block per e).
// Thread t owns column n = t of the 5 x 256 sim/K matrices (in registers).
// ---------------------------------------------------------------------------
__global__ void __launch_bounds__(TPB) k_sinkhorn(
    const float* __restrict__ gt_local)
{
    const int e = blockIdx.x;
    const int tid = threadIdx.x;         // == n
    const int w = tid >> 5;
    const int lane = tid & 31;

    __shared__ float sh_gn[M_];          // ||g_m||
    __shared__ float sred[8 * M_];       // per-warp partials for K@c
    __shared__ float sh_r[M_];           // row scaling vector
    __shared__ float sh_scalar[8];       // final reduction

    // gt_local row norms: warps 0..4, one row each
    if (w < M_) {
        const float* g = gt_local + ((size_t)e * M_ + w) * D_;
        float s = 0.f;
        for (int d = lane; d < D_; d += 32) {
            float v = g[d];
            s += v * v;
        }
        #pragma unroll
        for (int off = 16; off > 0; off >>= 1)
            s += __shfl_down_sync(0xFFFFFFFFu, s, off);
        if (lane == 0) sh_gn[w] = sqrtf(s);
    }
    __syncthreads();

    // Build sim[m][n] and K[m][n] in registers
    const float fn = fmaxf(sqrtf(g_fnorm2[e][tid]), 1e-12f);
    float simv[M_], Kv[M_];
    #pragma unroll
    for (int m = 0; m < M_; m++) {
        const float gn = fmaxf(sh_gn[m], 1e-12f);
        simv[m] = g_dotmn[e][m][tid] / (gn * fn);
        Kv[m] = __expf((simv[m] - 1.0f) * 10.0f);   // exp(-(1-sim)/0.1)
    }

    // Sinkhorn loop (mirrors the reference exactly)
    const float u = 1.0f / (float)M_;
    const float vv = 1.0f / (float)N_;
    float c = 1.0f;
    float r[M_] = {1.f, 1.f, 1.f, 1.f, 1.f};
    float err = 1e9f;

    for (int it = 0; it < 100 && err >= 0.01f; ++it) {
        // Kc[m] = sum_n K[m][n] * c[n]
        float p[M_];
        #pragma unroll
        for (int m = 0; m < M_; m++) p[m] = Kv[m] * c;
        #pragma unroll
        for (int off = 16; off > 0; off >>= 1) {
            #pragma unroll
            for (int m = 0; m < M_; m++)
                p[m] += __shfl_down_sync(0xFFFFFFFFu, p[m], off);
        }
        if (lane == 0) {
            #pragma unroll
            for (int m = 0; m < M_; m++) sred[w * M_ + m] = p[m];
        }
        __syncthreads();
        if (tid < M_) {
            float s = 0.f;
            #pragma unroll
            for (int ww = 0; ww < 8; ww++) s += sred[ww * M_ + tid];
            sh_r[tid] = u / s;           // r = u / (K @ c)
        }
        __syncthreads();
        // all threads: identical update of r, err, c  (uniform branch)
        float errs = 0.f;
        #pragma unroll
        for (int m = 0; m < M_; m++) {
            float rn = sh_r[m];
            errs += fabsf(rn - r[m]);
            r[m] = rn;
        }
        err = errs * (1.0f / (float)M_);
        float ktr = 0.f;
        #pragma unroll
        for (int m = 0; m < M_; m++) ktr += Kv[m] * r[m];
        c = vv / ktr;                    // c = v / (K^T @ r)
    }

    // ot = sum_{m,n} r[m]*c[n]*K[m][n]*sim[m][n]
    float t = 0.f;
    #pragma unroll
    for (int m = 0; m < M_; m++) t += r[m] * Kv[m] * simv[m];
    t *= c;
    #pragma unroll
    for (int off = 16; off > 0; off >>= 1)
        t += __shfl_down_sync(0xFFFFFFFFu, t, off);
    if (lane == 0) sh_scalar[w] = t;
    __syncthreads();
    if (tid == 0) {
        float s = 0.f;
        #pragma unroll
        for (int ww = 0; ww < 8; ww++) s += sh_scalar[ww];
        g_ot[e] = s;
    }
}

// ---------------------------------------------------------------------------
// Kernel 3: finalize — deterministic sum of partials + scalar combine
// ---------------------------------------------------------------------------
__global__ void __launch_bounds__(TPB) k_final(float* __restrict__ out)
{
    const int tid = threadIdx.x;
    __shared__ float sh[TPB];
    float s = 0.f;
    for (int i = tid; i < NB_ALL; i += TPB) s += g_dot_partial[i];
    sh[tid] = s;
    __syncthreads();
    #pragma unroll
    for (int st = TPB / 2; st > 0; st >>= 1) {
        if (tid < st) sh[tid] += sh[tid + st];
        __syncthreads();
    }
    if (tid == 0) {
        float loss_global = sh[0] / (float)(E_ * B_);
        float loss_local = (g_ot[0] + g_ot[1] + g_ot[2]) * 2.0f / (float)E_;
        out[0] = loss_global + 0.1f * loss_local;
    }
}

// ---------------------------------------------------------------------------
extern "C" void kernel_launch(void* const* d_in, const int* in_sizes, int n_in,
                              void* d_out, int out_size)
{
    const float* feature        = (const float*)d_in[0];
    const float* gt             = (const float*)d_in[1];
    const float* gt_local       = (const float*)d_in[2];
    const float* feature_local  = (const float*)d_in[3];
    float* out = (float*)d_out;

    k_main<<<NB_ALL, TPB>>>(feature, gt, gt_local, feature_local);
    k_sinkhorn<<<E_, TPB>>>(gt_local);
    k_final<<<1, TPB>>>(out);
}

// round 12
// speedup vs baseline: 1.1218x; 1.1218x over previous
#include <cuda_runtime.h>
#include <cuda_bf16.h>
#include <math.h>

// Problem constants (fixed by the reference setup_inputs)
#define E_  3
#define B_  4096
#define D_  1024
#define M_  5
#define N_  256

#define NB_DOT 512          // blocks for the big feature*gt reduction
#define NB_SIM 96           // 3 e * 32 blocks, each block = 8 warps, 1 n per warp
#define TPB 256

// 24 float4-pairs per thread, unrolled by 4 -> 6 outer iterations, no tail.
#define STRIDE (NB_DOT * TPB)

// Scratch (allocation-free rule: __device__ globals)
__device__ float g_dot_partial[NB_DOT];
__device__ float g_dotmn[E_][M_][N_];   // raw dot(gt_local[m], feature_local[n])
__device__ float g_fnorm2[E_][N_];      // ||f_n||^2
__device__ float g_ot[E_];

static __device__ __forceinline__ float dot4(float4 a, float4 b) {
    return a.x * b.x + a.y * b.y + a.z * b.z + a.w * b.w;
}

// ---------------------------------------------------------------------------
// Kernel 1: (a) blocks [0, NB_DOT): grid-strided float4 dot of feature*gt,
//               front-batched 8 LDG.128 per iteration for MLP;
//           (b) blocks [NB_DOT, NB_DOT+NB_SIM): sim raw dots + f-row norms.
// (Empirically fastest configuration: 18.94us / 20.26us across sessions.)
// ---------------------------------------------------------------------------
__global__ void __launch_bounds__(TPB, 4) k_main(
    const float* __restrict__ feature,
    const float* __restrict__ gt,
    const float* __restrict__ gt_local,
    const float* __restrict__ feature_local)
{
    const int b = blockIdx.x;
    const int tid = threadIdx.x;

    if (b < NB_DOT) {
        // ---- big streaming reduction: sum(feature * gt) ----
        const float4* fa = reinterpret_cast<const float4*>(feature);
        const float4* ga = reinterpret_cast<const float4*>(gt);
        int i = b * TPB + tid;
        float acc0 = 0.f, acc1 = 0.f, acc2 = 0.f, acc3 = 0.f;
        #pragma unroll 1
        for (int k = 0; k < 6; ++k) {
            // 8 independent 16B loads front-batched (read-once: evict-first)
            float4 x0 = __ldcs(&fa[i]);
            float4 x1 = __ldcs(&fa[i + STRIDE]);
            float4 x2 = __ldcs(&fa[i + 2 * STRIDE]);
            float4 x3 = __ldcs(&fa[i + 3 * STRIDE]);
            float4 y0 = __ldcs(&ga[i]);
            float4 y1 = __ldcs(&ga[i + STRIDE]);
            float4 y2 = __ldcs(&ga[i + 2 * STRIDE]);
            float4 y3 = __ldcs(&ga[i + 3 * STRIDE]);
            acc0 += dot4(x0, y0);
            acc1 += dot4(x1, y1);
            acc2 += dot4(x2, y2);
            acc3 += dot4(x3, y3);
            i += 4 * STRIDE;
        }
        float acc = (acc0 + acc1) + (acc2 + acc3);

        __shared__ float sh[TPB];
        sh[tid] = acc;
        __syncthreads();
        #pragma unroll
        for (int s = TPB / 2; s > 0; s >>= 1) {
            if (tid < s) sh[tid] += sh[tid + s];
            __syncthreads();
        }
        if (tid == 0) g_dot_partial[b] = sh[0];
    } else {
        // ---- sim raw dots + feature_local row norms ----
        const int sb = b - NB_DOT;          // 0..95
        const int e  = sb / 32;             // 3 extractors
        const int w  = tid >> 5;            // warp id 0..7
        const int lane = tid & 31;
        const int n  = (sb % 32) * 8 + w;   // 0..255

        const float* __restrict__ f = feature_local + ((size_t)e * N_ + n) * D_;
        const float* __restrict__ g = gt_local + (size_t)e * M_ * D_;

        float acc[M_] = {0.f, 0.f, 0.f, 0.f, 0.f};
        float fn = 0.f;
        for (int d = lane; d < D_; d += 32) {
            float fv = f[d];
            fn += fv * fv;
            #pragma unroll
            for (int m = 0; m < M_; m++)
                acc[m] += g[m * D_ + d] * fv;
        }
        #pragma unroll
        for (int off = 16; off > 0; off >>= 1) {
            fn += __shfl_down_sync(0xFFFFFFFFu, fn, off);
            #pragma unroll
            for (int m = 0; m < M_; m++)
                acc[m] += __shfl_down_sync(0xFFFFFFFFu, acc[m], off);
        }
        if (lane == 0) {
            #pragma unroll
            for (int m = 0; m < M_; m++)
                g_dotmn[e][m][n] = acc[m];
            g_fnorm2[e][n] = fn;
        }
    }
}

// ---------------------------------------------------------------------------
// Kernel 2: per-extractor Sinkhorn (one 256-thread block per e).
// Thread t owns column n = t of the 5 x 256 sim/K matrices (in registers).
// ---------------------------------------------------------------------------
__global__ void __launch_bounds__(TPB) k_sinkhorn(
    const float* __restrict__ gt_local)
{
    const int e = blockIdx.x;
    const int tid = threadIdx.x;         // == n
    const int w = tid >> 5;
    const int lane = tid & 31;

    __shared__ float sh_gn[M_];          // ||g_m||
    __shared__ float sred[8 * M_];       // per-warp partials for K@c
    __shared__ float sh_r[M_];           // row scaling vector
    __shared__ float sh_scalar[8];       // final reduction

    // gt_local row norms: warps 0..4, one row each
    if (w < M_) {
        const float* g = gt_local + ((size_t)e * M_ + w) * D_;
        float s = 0.f;
        for (int d = lane; d < D_; d += 32) {
            float v = g[d];
            s += v * v;
        }
        #pragma unroll
        for (int off = 16; off > 0; off >>= 1)
            s += __shfl_down_sync(0xFFFFFFFFu, s, off);
        if (lane == 0) sh_gn[w] = sqrtf(s);
    }
    __syncthreads();

    // Build sim[m][n] and K[m][n] in registers
    const float fn = fmaxf(sqrtf(g_fnorm2[e][tid]), 1e-12f);
    float simv[M_], Kv[M_];
    #pragma unroll
    for (int m = 0; m < M_; m++) {
        const float gn = fmaxf(sh_gn[m], 1e-12f);
        simv[m] = g_dotmn[e][m][tid] / (gn * fn);
        Kv[m] = __expf((simv[m] - 1.0f) * 10.0f);   // exp(-(1-sim)/0.1)
    }

    // Sinkhorn loop (mirrors the reference exactly)
    const float u = 1.0f / (float)M_;
    const float vv = 1.0f / (float)N_;
    float c = 1.0f;
    float r[M_] = {1.f, 1.f, 1.f, 1.f, 1.f};
    float err = 1e9f;

    for (int it = 0; it < 100 && err >= 0.01f; ++it) {
        // Kc[m] = sum_n K[m][n] * c[n]
        float p[M_];
        #pragma unroll
        for (int m = 0; m < M_; m++) p[m] = Kv[m] * c;
        #pragma unroll
        for (int off = 16; off > 0; off >>= 1) {
            #pragma unroll
            for (int m = 0; m < M_; m++)
                p[m] += __shfl_down_sync(0xFFFFFFFFu, p[m], off);
        }
        if (lane == 0) {
            #pragma unroll
            for (int m = 0; m < M_; m++) sred[w * M_ + m] = p[m];
        }
        __syncthreads();
        if (tid < M_) {
            float s = 0.f;
            #pragma unroll
            for (int ww = 0; ww < 8; ww++) s += sred[ww * M_ + tid];
            sh_r[tid] = u / s;           // r = u / (K @ c)
        }
        __syncthreads();
        // all threads: identical update of r, err, c  (uniform branch)
        float errs = 0.f;
        #pragma unroll
        for (int m = 0; m < M_; m++) {
            float rn = sh_r[m];
            errs += fabsf(rn - r[m]);
            r[m] = rn;
        }
        err = errs * (1.0f / (float)M_);
        float ktr = 0.f;
        #pragma unroll
        for (int m = 0; m < M_; m++) ktr += Kv[m] * r[m];
        c = vv / ktr;                    // c = v / (K^T @ r)
    }

    // ot = sum_{m,n} r[m]*c[n]*K[m][n]*sim[m][n]
    float t = 0.f;
    #pragma unroll
    for (int m = 0; m < M_; m++) t += r[m] * Kv[m] * simv[m];
    t *= c;
    #pragma unroll
    for (int off = 16; off > 0; off >>= 1)
        t += __shfl_down_sync(0xFFFFFFFFu, t, off);
    if (lane == 0) sh_scalar[w] = t;
    __syncthreads();
    if (tid == 0) {
        float s = 0.f;
        #pragma unroll
        for (int ww = 0; ww < 8; ww++) s += sh_scalar[ww];
        g_ot[e] = s;
    }
}

// ---------------------------------------------------------------------------
// Kernel 3: finalize — deterministic sum of partials + scalar combine
// ---------------------------------------------------------------------------
__global__ void __launch_bounds__(TPB) k_final(float* __restrict__ out)
{
    const int tid = threadIdx.x;
    __shared__ float sh[TPB];
    float s = 0.f;
    for (int i = tid; i < NB_DOT; i += TPB) s += g_dot_partial[i];
    sh[tid] = s;
    __syncthreads();
    #pragma unroll
    for (int st = TPB / 2; st > 0; st >>= 1) {
        if (tid < st) sh[tid] += sh[tid + st];
        __syncthreads();
    }
    if (tid == 0) {
        float loss_global = sh[0] / (float)(E_ * B_);
        float loss_local = (g_ot[0] + g_ot[1] + g_ot[2]) * 2.0f / (float)E_;
        out[0] = loss_global + 0.1f * loss_local;
    }
}

// ---------------------------------------------------------------------------
extern "C" void kernel_launch(void* const* d_in, const int* in_sizes, int n_in,
                              void* d_out, int out_size)
{
    const float* feature        = (const float*)d_in[0];
    const float* gt             = (const float*)d_in[1];
    const float* gt_local       = (const float*)d_in[2];
    const float* feature_local  = (const float*)d_in[3];
    float* out = (float*)d_out;

    k_main<<<NB_DOT + NB_SIM, TPB>>>(feature, gt, gt_local, feature_local);
    k_sinkhorn<<<E_, TPB>>>(gt_local);
    k_final<<<1, TPB>>>(out);
}